// round 12
// baseline (speedup 1.0000x reference)
#include <cuda_runtime.h>

// SpikingLayer, R10: R2's fp64 orbit BIT-IDENTICAL, fp64-pipe ops 2300 -> 1400.
//
// R9 confirmed the cost model: dur scales with fp64-pipe op count (DFMA + cvt,
// ~18.4 cyc/SM each); everything else is idle (DRAM 9.5%, issue 11.6%).
// Two provably-bitwise-exact removals:
//
// 1) ul-chain (400 DFMA) removed: ul(t) = fma(Ad, ul(t-1), c2d(t)) with
//    c2d(t) = c1d(t-100) and fma(Ad,0,c)==c exact  =>  ul(t) == u(t-100)
//    BITWISE (identical fma sequence from 0). Serve it from a 100-deep
//    per-thread circular buffer of u in shared memory (slot t%100 read
//    before overwrite). 32-thr blocks: 25.6 KB static smem, conflict-free.
//
// 2) F2F f64->f32 (500 ops) removed: RN conversion emulated exactly on the
//    ALU pipe (shift + round-to-nearest-even + exponent rebias on raw bits).
//    |w| < 2^-126 -> +/-0: differs from true RN by <= 2^-126 in vm, which
//    cannot flip (vt >= 1.0) since that needs vm ~= 1. Spikes (the only
//    output) unchanged; r then bit-identical by induction.
//
// Remaining fp64/step: u-fma, inner fma(-E10,ul,u), w-fma (phases C/D);
// u-fma, w-fma (A/B). Total = 200 + 1200 = 1400.
// Bonus: lags 100/150 now come from the buffer -> 1 LDG/step + 64-bit
// shift history for lag 50.

#define SNN_S 65536
#define SNN_T 500

// Exact RN f64->f32 on integer pipe (normal f32 range; underflow -> signed 0).
__device__ __forceinline__ float snn_d2f_rn(double w) {
    unsigned long long b   = (unsigned long long)__double_as_longlong(w);
    unsigned long long mag = b & 0x7fffffffffffffffull;
    unsigned int sign = (unsigned int)(b >> 32) & 0x80000000u;
    if (mag < (897ull << 52)) return __uint_as_float(sign);  // |w| < 2^-126
    unsigned long long sh  = mag >> 29;
    unsigned long long rem = mag & 0x1fffffffull;
    sh += (rem > 0x10000000ull) | ((rem == 0x10000000ull) & (sh & 1ull));
    return __uint_as_float((unsigned int)(sh - (896ull << 23)) | sign);
}

__global__ __launch_bounds__(32)
void SpikingLayer_90202903151092_kernel(const unsigned* __restrict__ xb,
                                        float* __restrict__ out) {
    __shared__ double ubuf[100 * 32];          // u history: slot*32 + tid
    const int tid = threadIdx.x;
    const int id  = blockIdx.x * 32 + tid;     // one neuron per thread

    const double Ad  = 0.81873075307798185867;     // exp(-1/5)
    const double Bd  = 0.90483741803595957316;     // exp(-1/10)
    const double E10 = 4.5399929762484851536e-05;  // exp(-10), f64
    constexpr float A50f = 4.5399929762484851536e-05f;
    const float ALPH = 0.90483741803595957316f;

    // the 4 exact values of (double)fmaf(-A50f, x50, x0), x0,x50 in {0,1}
    constexpr double C00 = 0.0;
    constexpr double C10 = 1.0;
    constexpr double C01 = -(double)A50f;
    constexpr double C11 = (double)((float)(1.0 - (double)A50f));

    double u = 0.0, w = 0.0;
    float  r = 0.0f;
    unsigned long long h0 = 0;                 // bit j = x(t-1-j): lag-50 source
    int slot = 0;                              // t % 100

    const unsigned* xp = xb + id;              // x in {0.0f,1.0f}: bits != 0 iff 1.0f
    float*          op = out + id;

#define SNN_TAIL()                                           \
    {                                                        \
        float vm = snn_d2f_rn(w);                            \
        float vt = vm + r;                                   \
        float s  = (vt >= 1.0f) ? 1.0f : 0.0f;               \
        r = (r - s) * ALPH;                                  \
        op[t * SNN_S] = s;                                   \
        h0 = (h0 << 1) | (unsigned long long)b0;             \
        slot = (slot == 99) ? 0 : slot + 1;                  \
    }

    // Phase A: t in [0,50)
    #pragma unroll 5
    for (int t = 0; t < 50; ++t) {
        int b0 = (xp[t * SNN_S] != 0u);
        u = fma(Ad, u, b0 ? C10 : C00);
        ubuf[slot * 32 + tid] = u;
        w = fma(Bd, w, u);
        SNN_TAIL();
    }

    // Phase B: t in [50,100)
    #pragma unroll 5
    for (int t = 50; t < 100; ++t) {
        int b0  = (xp[t * SNN_S] != 0u);
        int b50 = (int)((h0 >> 49) & 1ull);
        double c1d = b0 ? (b50 ? C11 : C10) : (b50 ? C01 : C00);
        u = fma(Ad, u, c1d);
        ubuf[slot * 32 + tid] = u;
        w = fma(Bd, w, u);
        SNN_TAIL();
    }

    // Phases C+D: t in [100,500) — ul(t) == u(t-100) from the buffer
    // (R2's phase C c2d = b100?C10:C00 == phase A's c1d at t-100;
    //  phase D c2d 4-way(b100,b150) == phase B/D's c1d at t-100: identical.)
    #pragma unroll 5
    for (int t = 100; t < SNN_T; ++t) {
        int b0  = (xp[t * SNN_S] != 0u);
        int b50 = (int)((h0 >> 49) & 1ull);
        double c1d = b0 ? (b50 ? C11 : C10) : (b50 ? C01 : C00);
        double ul = ubuf[slot * 32 + tid];     // u(t-100), read before overwrite
        u = fma(Ad, u, c1d);
        ubuf[slot * 32 + tid] = u;
        w = fma(Bd, w, fma(-E10, ul, u));
        SNN_TAIL();
    }
#undef SNN_TAIL
}

extern "C" void kernel_launch(void* const* d_in, const int* in_sizes, int n_in,
                              void* d_out, int out_size) {
    const unsigned* xb = (const unsigned*)d_in[0];  // binary_input (T,B,1,N) as bits
    // d_in[1] = epsp_kernel (1,149): algebraically folded into the recurrence
    float* out = (float*)d_out;                     // spikes (T,B,N) float32
    SpikingLayer_90202903151092_kernel<<<2048, 32>>>(xb, out);
}